// round 5
// baseline (speedup 1.0000x reference)
#include <cuda_runtime.h>
#include <math.h>

#define BATCH 2
#define SEQ   2048
#define CDIM  1024
#define HEADS 16
#define HD    64
#define SCALE 0.125f
#define LOG2E 1.44269504088896f

#define BHN   (BATCH*HEADS)
#define ROWS  (BATCH*SEQ)
#define QKVN  (3*CDIM)

// tf32 scratch (pre-converted operands)
__device__ unsigned g_Xt[ROWS*CDIM];
__device__ unsigned g_Wqkvt[CDIM*QKVN];
__device__ unsigned g_Wprojt[CDIM*CDIM];
__device__ unsigned g_Qt[BATCH*HEADS*SEQ*HD];   // pre-scaled by SCALE*LOG2E
__device__ unsigned g_Kt[BATCH*HEADS*SEQ*HD];
__device__ unsigned g_Vt[BATCH*HEADS*SEQ*HD];
__device__ unsigned g_Ft[ROWS*CDIM];            // tf32(att2 + f)
__device__ float    g_att_fallback[ROWS*CDIM];

// ---------------------------------------------------------------------------
// helpers
// ---------------------------------------------------------------------------
__device__ __forceinline__ unsigned f2tf32(float x) {
    unsigned u;
    asm("cvt.rna.tf32.f32 %0, %1;" : "=r"(u) : "f"(x));
    return u;
}

__device__ __forceinline__ void mma_tf32(float* d,
                                         unsigned a0, unsigned a1, unsigned a2, unsigned a3,
                                         unsigned b0, unsigned b1) {
    asm volatile(
        "mma.sync.aligned.m16n8k8.row.col.f32.tf32.tf32.f32 "
        "{%0,%1,%2,%3}, {%4,%5,%6,%7}, {%8,%9}, {%0,%1,%2,%3};"
        : "+f"(d[0]), "+f"(d[1]), "+f"(d[2]), "+f"(d[3])
        : "r"(a0), "r"(a1), "r"(a2), "r"(a3), "r"(b0), "r"(b1));
}

__device__ __forceinline__ unsigned sptr(const void* p) {
    return (unsigned)__cvta_generic_to_shared(p);
}
#define CPA(dst, src) asm volatile("cp.async.cg.shared.global [%0], [%1], 16;" :: "r"(dst), "l"(src))
#define CPC()         asm volatile("cp.async.commit_group;")
#define CPW(n)        asm volatile("cp.async.wait_group %0;" :: "n"(n))

// ---------------------------------------------------------------------------
// prep kernels
// ---------------------------------------------------------------------------
__global__ void cvt_tf32_k(const float4* __restrict__ src, uint4* __restrict__ dst, int n4) {
    int i = blockIdx.x * blockDim.x + threadIdx.x;
    if (i < n4) {
        float4 v = src[i];
        dst[i] = make_uint4(f2tf32(v.x), f2tf32(v.y), f2tf32(v.z), f2tf32(v.w));
    }
}

__global__ void fuse_tf32_k(const float4* __restrict__ a, const float4* __restrict__ f,
                            uint4* __restrict__ dst, int n4) {
    int i = blockIdx.x * blockDim.x + threadIdx.x;
    if (i < n4) {
        float4 x = a[i], y = f[i];
        dst[i] = make_uint4(f2tf32(x.x + y.x), f2tf32(x.y + y.y),
                            f2tf32(x.z + y.z), f2tf32(x.w + y.w));
    }
}

// ---------------------------------------------------------------------------
// Kernel 1: QKV GEMM, 128x128 tile, BK=16, 3-stage cp.async pipeline.
// smem: sA[3][128][20] ([m][k], stride 20), sB[3][16][136] ([k][n], stride 136).
// ---------------------------------------------------------------------------
#define AST 20
#define BST 136
#define GEMM_SMEM ((3*128*AST + 3*16*BST) * 4)

__global__ __launch_bounds__(128, 2) void qkv_tc() {
    extern __shared__ unsigned sm[];
    unsigned* sA = sm;
    unsigned* sB = sm + 3 * 128 * AST;

    const int tid = threadIdx.x;
    const int lane = tid & 31;
    const int w = tid >> 5;
    const int g = lane >> 2, t = lane & 3;
    const int wm = w & 1, wn = w >> 1;

    const int m0 = blockIdx.y * 128;
    const int n0 = blockIdx.x * 128;

    float acc[4][8][4];
#pragma unroll
    for (int mt = 0; mt < 4; mt++)
#pragma unroll
        for (int nt = 0; nt < 8; nt++)
#pragma unroll
            for (int i = 0; i < 4; i++) acc[mt][nt][i] = 0.f;

    // producers
    const unsigned* Xrow = g_Xt + (size_t)(m0 + tid) * CDIM;                 // 4 chunks/row
    const unsigned* Wrow = g_Wqkvt + (size_t)(tid >> 3) * QKVN + n0 + 4 * (tid & 7);
    const unsigned saB = sptr(sA) + tid * AST * 4;
    const unsigned sbB = sptr(sB) + ((tid >> 3) * BST + 4 * (tid & 7)) * 4;

#define QKV_LOAD(st, k0)                                                      \
    {                                                                         \
        unsigned da = saB + (st) * 128 * AST * 4;                             \
        _Pragma("unroll") for (int c = 0; c < 4; c++)                         \
            CPA(da + 16 * c, Xrow + (k0) + 4 * c);                            \
        unsigned db = sbB + (st) * 16 * BST * 4;                              \
        _Pragma("unroll") for (int j = 0; j < 4; j++)                         \
            CPA(db + 128 * j, Wrow + (size_t)(k0) * QKVN + 32 * j);           \
    }

    QKV_LOAD(0, 0); CPC();
    QKV_LOAD(1, 16); CPC();

    int buf = 0;
    for (int it = 0; it < 64; it++) {
        CPW(1);
        __syncthreads();
        if (it + 2 < 64) {
            int st = (it + 2) % 3;
            QKV_LOAD(st, (it + 2) * 16); CPC();
        } else {
            CPC();  // keep group count monotone for CPW(1) semantics
        }

        const unsigned* A = sA + buf * 128 * AST;
        const unsigned* B = sB + buf * 16 * BST;
#pragma unroll
        for (int kt = 0; kt < 2; kt++) {
            unsigned af[4][4];
#pragma unroll
            for (int mt = 0; mt < 4; mt++) {
                int mr = wm * 64 + mt * 16;
                const unsigned* a0 = A + (mr + g) * AST + 8 * kt + t;
                const unsigned* a1 = A + (mr + g + 8) * AST + 8 * kt + t;
                af[mt][0] = a0[0]; af[mt][1] = a1[0];
                af[mt][2] = a0[4]; af[mt][3] = a1[4];
            }
#pragma unroll
            for (int nt = 0; nt < 8; nt++) {
                int nc = wn * 64 + nt * 8 + g;
                unsigned b0 = B[(8 * kt + t) * BST + nc];
                unsigned b1 = B[(8 * kt + t + 4) * BST + nc];
#pragma unroll
                for (int mt = 0; mt < 4; mt++)
                    mma_tf32(acc[mt][nt], af[mt][0], af[mt][1], af[mt][2], af[mt][3], b0, b1);
            }
        }
        buf = (buf + 1) % 3;
    }

    // scatter epilogue -> tf32 Q (pre-scaled), K, V in (B,H,N,D)
    const float QF = SCALE * LOG2E;
#pragma unroll
    for (int mt = 0; mt < 4; mt++) {
#pragma unroll
        for (int nt = 0; nt < 8; nt++) {
            int col = n0 + wn * 64 + nt * 8 + 2 * t;
            int s = col >> 10;
            int h = (col >> 6) & 15;
            int dd = col & 63;
            unsigned* dst = (s == 0) ? g_Qt : (s == 1) ? g_Kt : g_Vt;
            float sc = (s == 0) ? QF : 1.f;
            int row0 = m0 + wm * 64 + mt * 16 + g;
#pragma unroll
            for (int half = 0; half < 2; half++) {
                int row = row0 + 8 * half;
                int b = row >> 11, n = row & 2047;
                unsigned* p = dst + ((((size_t)b * HEADS + h) * SEQ + n) * HD + dd);
                p[0] = f2tf32(acc[mt][nt][2 * half] * sc);
                p[1] = f2tf32(acc[mt][nt][2 * half + 1] * sc);
            }
        }
    }
}

// ---------------------------------------------------------------------------
// Kernel 2: flash attention, double-buffered cp.async K/V tiles, tf32 inputs.
// ---------------------------------------------------------------------------
#define SKS 68
#define SVS 72
#define FLASH_SMEM ((2*64*SKS + 2*64*SVS + 64*SKS) * 4)

__global__ __launch_bounds__(128) void flash_attn_tc(float* __restrict__ out2) {
    extern __shared__ unsigned sm[];
    unsigned* sK = sm;                       // [2][64][SKS]
    unsigned* sV = sm + 2 * 64 * SKS;        // [2][64][SVS]
    unsigned* sP = sm + 2 * 64 * SKS + 2 * 64 * SVS;

    const int tid = threadIdx.x;
    const int lane = tid & 31;
    const int w = tid >> 5;
    const int g = lane >> 2;
    const int t = lane & 3;

    const int bh = blockIdx.y;
    const int q0 = blockIdx.x * 64;

    // Q fragments (already tf32, pre-scaled)
    unsigned qa[8][4];
    {
        const unsigned* p0 = g_Qt + ((size_t)bh * SEQ + (q0 + w * 16 + g)) * HD;
        const unsigned* p1 = p0 + 8 * HD;
#pragma unroll
        for (int kt = 0; kt < 8; kt++) {
            qa[kt][0] = p0[8 * kt + t];
            qa[kt][1] = p1[8 * kt + t];
            qa[kt][2] = p0[8 * kt + t + 4];
            qa[kt][3] = p1[8 * kt + t + 4];
        }
    }

    float o[8][4];
#pragma unroll
    for (int nt = 0; nt < 8; nt++)
#pragma unroll
        for (int i = 0; i < 4; i++) o[nt][i] = 0.f;
    float m0 = -1e30f, m1 = -1e30f, l0 = 0.f, l1 = 0.f;

    // producers: thread -> row tid>>1, half (tid&1)*32 words, 8 chunks
    const unsigned* Kb = g_Kt + ((size_t)bh * SEQ + (tid >> 1)) * HD + (tid & 1) * 32;
    const unsigned* Vb = g_Vt + ((size_t)bh * SEQ + (tid >> 1)) * HD + (tid & 1) * 32;
    const unsigned skB = sptr(sK) + ((tid >> 1) * SKS + (tid & 1) * 32) * 4;
    const unsigned svB = sptr(sV) + ((tid >> 1) * SVS + (tid & 1) * 32) * 4;

#define KV_LOAD(st, kv)                                                      \
    {                                                                        \
        unsigned dk = skB + (st) * 64 * SKS * 4;                             \
        const unsigned* sk = Kb + (size_t)(kv) * 64 * HD;                    \
        _Pragma("unroll") for (int j = 0; j < 8; j++) CPA(dk + 16 * j, sk + 4 * j); \
        unsigned dv = svB + (st) * 64 * SVS * 4;                             \
        const unsigned* sv2 = Vb + (size_t)(kv) * 64 * HD;                   \
        _Pragma("unroll") for (int j = 0; j < 8; j++) CPA(dv + 16 * j, sv2 + 4 * j); \
    }

    KV_LOAD(0, 0); CPC();

    int buf = 0;
    for (int kv = 0; kv < SEQ / 64; kv++) {
        if (kv + 1 < SEQ / 64) { KV_LOAD(buf ^ 1, kv + 1); CPC(); CPW(1); }
        else                   { CPW(0); }
        __syncthreads();

        const unsigned* K = sK + buf * 64 * SKS;
        const unsigned* V = sV + buf * 64 * SVS;

        float s[8][4];
#pragma unroll
        for (int nt = 0; nt < 8; nt++)
#pragma unroll
            for (int i = 0; i < 4; i++) s[nt][i] = 0.f;

#pragma unroll
        for (int kt = 0; kt < 8; kt++) {
#pragma unroll
            for (int nt = 0; nt < 8; nt++) {
                unsigned b0 = K[(8 * nt + g) * SKS + 8 * kt + t];
                unsigned b1 = K[(8 * nt + g) * SKS + 8 * kt + t + 4];
                mma_tf32(s[nt], qa[kt][0], qa[kt][1], qa[kt][2], qa[kt][3], b0, b1);
            }
        }

        float rx0 = -1e30f, rx1 = -1e30f;
#pragma unroll
        for (int nt = 0; nt < 8; nt++) {
            rx0 = fmaxf(rx0, fmaxf(s[nt][0], s[nt][1]));
            rx1 = fmaxf(rx1, fmaxf(s[nt][2], s[nt][3]));
        }
        rx0 = fmaxf(rx0, __shfl_xor_sync(0xffffffffu, rx0, 1));
        rx0 = fmaxf(rx0, __shfl_xor_sync(0xffffffffu, rx0, 2));
        rx1 = fmaxf(rx1, __shfl_xor_sync(0xffffffffu, rx1, 1));
        rx1 = fmaxf(rx1, __shfl_xor_sync(0xffffffffu, rx1, 2));

        float nm0 = fmaxf(m0, rx0), nm1 = fmaxf(m1, rx1);
        float c0 = exp2f(m0 - nm0), c1 = exp2f(m1 - nm1);
        m0 = nm0; m1 = nm1;

        float ps0 = 0.f, ps1 = 0.f;
#pragma unroll
        for (int nt = 0; nt < 8; nt++) {
            s[nt][0] = exp2f(s[nt][0] - nm0);
            s[nt][1] = exp2f(s[nt][1] - nm0);
            s[nt][2] = exp2f(s[nt][2] - nm1);
            s[nt][3] = exp2f(s[nt][3] - nm1);
            ps0 += s[nt][0] + s[nt][1];
            ps1 += s[nt][2] + s[nt][3];
        }
        ps0 += __shfl_xor_sync(0xffffffffu, ps0, 1);
        ps0 += __shfl_xor_sync(0xffffffffu, ps0, 2);
        ps1 += __shfl_xor_sync(0xffffffffu, ps1, 1);
        ps1 += __shfl_xor_sync(0xffffffffu, ps1, 2);
        l0 = l0 * c0 + ps0;
        l1 = l1 * c1 + ps1;

#pragma unroll
        for (int nt = 0; nt < 8; nt++) {
            o[nt][0] *= c0; o[nt][1] *= c0;
            o[nt][2] *= c1; o[nt][3] *= c1;
        }

        unsigned* pr0 = sP + (w * 16 + g) * SKS;
        unsigned* pr1 = pr0 + 8 * SKS;
#pragma unroll
        for (int nt = 0; nt < 8; nt++) {
            *(uint2*)(pr0 + 8 * nt + 2 * t) = make_uint2(f2tf32(s[nt][0]), f2tf32(s[nt][1]));
            *(uint2*)(pr1 + 8 * nt + 2 * t) = make_uint2(f2tf32(s[nt][2]), f2tf32(s[nt][3]));
        }
        __syncwarp();

#pragma unroll
        for (int kt = 0; kt < 8; kt++) {
            unsigned pa0 = pr0[8 * kt + t];
            unsigned pa1 = pr1[8 * kt + t];
            unsigned pa2 = pr0[8 * kt + t + 4];
            unsigned pa3 = pr1[8 * kt + t + 4];
#pragma unroll
            for (int nt = 0; nt < 8; nt++) {
                unsigned b0 = V[(8 * kt + t) * SVS + 8 * nt + g];
                unsigned b1 = V[(8 * kt + t + 4) * SVS + 8 * nt + g];
                mma_tf32(o[nt], pa0, pa1, pa2, pa3, b0, b1);
            }
        }
        __syncthreads();
        buf ^= 1;
    }

    const float inv0 = 1.f / l0, inv1 = 1.f / l1;
    const int b = bh >> 4, h = bh & 15;
    const int r0 = q0 + w * 16 + g;
    float* op0 = out2 + ((size_t)b * SEQ + r0) * CDIM + h * HD;
    float* op1 = op0 + (size_t)8 * CDIM;
#pragma unroll
    for (int nt = 0; nt < 8; nt++) {
        *(float2*)(op0 + 8 * nt + 2 * t) = make_float2(o[nt][0] * inv0, o[nt][1] * inv0);
        *(float2*)(op1 + 8 * nt + 2 * t) = make_float2(o[nt][2] * inv1, o[nt][3] * inv1);
    }
}

// ---------------------------------------------------------------------------
// Kernel 3: proj GEMM (tf32, cp.async pipeline). out = fusedt @ Wproj + b
// ---------------------------------------------------------------------------
__global__ __launch_bounds__(128, 2) void proj_tc(const float* __restrict__ bias,
                                                  float* __restrict__ out) {
    extern __shared__ unsigned sm[];
    unsigned* sA = sm;
    unsigned* sB = sm + 3 * 128 * AST;

    const int tid = threadIdx.x;
    const int lane = tid & 31;
    const int w = tid >> 5;
    const int g = lane >> 2, t = lane & 3;
    const int wm = w & 1, wn = w >> 1;

    const int m0 = blockIdx.y * 128;
    const int n0 = blockIdx.x * 128;

    float acc[4][8][4];
#pragma unroll
    for (int mt = 0; mt < 4; mt++)
#pragma unroll
        for (int nt = 0; nt < 8; nt++)
#pragma unroll
            for (int i = 0; i < 4; i++) acc[mt][nt][i] = 0.f;

    const unsigned* Arow = g_Ft + (size_t)(m0 + tid) * CDIM;
    const unsigned* Wrow = g_Wprojt + (size_t)(tid >> 3) * CDIM + n0 + 4 * (tid & 7);
    const unsigned saB = sptr(sA) + tid * AST * 4;
    const unsigned sbB = sptr(sB) + ((tid >> 3) * BST + 4 * (tid & 7)) * 4;

#define PROJ_LOAD(st, k0)                                                     \
    {                                                                         \
        unsigned da = saB + (st) * 128 * AST * 4;                             \
        _Pragma("unroll") for (int c = 0; c < 4; c++)                         \
            CPA(da + 16 * c, Arow + (k0) + 4 * c);                            \
        unsigned db = sbB + (st) * 16 * BST * 4;                              \
        _Pragma("unroll") for (int j = 0; j < 4; j++)                         \
            CPA(db + 128 * j, Wrow + (size_t)(k0) * CDIM + 32 * j);           \
    }

    PROJ_LOAD(0, 0); CPC();
    PROJ_LOAD(1, 16); CPC();

    int buf = 0;
    for (int it = 0; it < 64; it++) {
        CPW(1);
        __syncthreads();
        if (it + 2 < 64) {
            int st = (it + 2) % 3;
            PROJ_LOAD(st, (it + 2) * 16); CPC();
        } else {
            CPC();
        }

        const unsigned* A = sA + buf * 128 * AST;
        const unsigned* B = sB + buf * 16 * BST;
#pragma unroll
        for (int kt = 0; kt < 2; kt++) {
            unsigned af[4][4];
#pragma unroll
            for (int mt = 0; mt < 4; mt++) {
                int mr = wm * 64 + mt * 16;
                const unsigned* a0 = A + (mr + g) * AST + 8 * kt + t;
                const unsigned* a1 = A + (mr + g + 8) * AST + 8 * kt + t;
                af[mt][0] = a0[0]; af[mt][1] = a1[0];
                af[mt][2] = a0[4]; af[mt][3] = a1[4];
            }
#pragma unroll
            for (int nt = 0; nt < 8; nt++) {
                int nc = wn * 64 + nt * 8 + g;
                unsigned b0 = B[(8 * kt + t) * BST + nc];
                unsigned b1 = B[(8 * kt + t + 4) * BST + nc];
#pragma unroll
                for (int mt = 0; mt < 4; mt++)
                    mma_tf32(acc[mt][nt], af[mt][0], af[mt][1], af[mt][2], af[mt][3], b0, b1);
            }
        }
        buf = (buf + 1) % 3;
    }

#pragma unroll
    for (int mt = 0; mt < 4; mt++) {
#pragma unroll
        for (int nt = 0; nt < 8; nt++) {
            int col = n0 + wn * 64 + nt * 8 + 2 * t;
            float2 bb = *(const float2*)&bias[col];
            int row0 = m0 + wm * 64 + mt * 16 + g;
            float* p0 = out + (size_t)row0 * CDIM + col;
            float* p1 = out + (size_t)(row0 + 8) * CDIM + col;
            *(float2*)p0 = make_float2(acc[mt][nt][0] + bb.x, acc[mt][nt][1] + bb.y);
            *(float2*)p1 = make_float2(acc[mt][nt][2] + bb.x, acc[mt][nt][3] + bb.y);
        }
    }
}

// ---------------------------------------------------------------------------
extern "C" void kernel_launch(void* const* d_in, const int* in_sizes, int n_in,
                              void* d_out, int out_size) {
    const float* x     = (const float*)d_in[0];
    const float* f     = (const float*)d_in[1];
    const float* Wqkv  = (const float*)d_in[2];
    const float* Wproj = (const float*)d_in[3];
    const float* bproj = (const float*)d_in[4];
    float* out = (float*)d_out;

    const size_t half = (size_t)BATCH * SEQ * CDIM;
    float* att2;
    if ((size_t)out_size >= 2 * half) {
        att2 = out + half;
    } else {
        cudaGetSymbolAddress((void**)&att2, g_att_fallback);
    }

    void *pXt, *pWqt, *pWpt, *pFt;
    cudaGetSymbolAddress(&pXt, g_Xt);
    cudaGetSymbolAddress(&pWqt, g_Wqkvt);
    cudaGetSymbolAddress(&pWpt, g_Wprojt);
    cudaGetSymbolAddress(&pFt, g_Ft);

    cudaFuncSetAttribute(qkv_tc, cudaFuncAttributeMaxDynamicSharedMemorySize, GEMM_SMEM);
    cudaFuncSetAttribute(proj_tc, cudaFuncAttributeMaxDynamicSharedMemorySize, GEMM_SMEM);
    cudaFuncSetAttribute(flash_attn_tc, cudaFuncAttributeMaxDynamicSharedMemorySize, FLASH_SMEM);

    // prep: tf32 conversions
    {
        int n4 = ROWS * CDIM / 4;
        cvt_tf32_k<<<(n4 + 255) / 256, 256>>>((const float4*)x, (uint4*)pXt, n4);
        n4 = CDIM * QKVN / 4;
        cvt_tf32_k<<<(n4 + 255) / 256, 256>>>((const float4*)Wqkv, (uint4*)pWqt, n4);
        n4 = CDIM * CDIM / 4;
        cvt_tf32_k<<<(n4 + 255) / 256, 256>>>((const float4*)Wproj, (uint4*)pWpt, n4);
    }

    qkv_tc<<<dim3(QKVN / 128, ROWS / 128), 128, GEMM_SMEM>>>();
    flash_attn_tc<<<dim3(SEQ / 64, BHN), 128, FLASH_SMEM>>>(att2);
    {
        int n4 = ROWS * CDIM / 4;
        fuse_tf32_k<<<(n4 + 255) / 256, 256>>>((const float4*)att2, (const float4*)f,
                                               (uint4*)pFt, n4);
    }
    proj_tc<<<dim3(CDIM / 128, ROWS / 128), 128, GEMM_SMEM>>>(bproj, out);
}

// round 6
// speedup vs baseline: 1.4849x; 1.4849x over previous
#include <cuda_runtime.h>
#include <math.h>

#define BATCH 2
#define SEQ   2048
#define CDIM  1024
#define HEADS 16
#define HD    64
#define SCALE 0.125f
#define LOG2E 1.44269504088896f

#define BHN   (BATCH*HEADS)
#define ROWS  (BATCH*SEQ)
#define QKVN  (3*CDIM)

// tf32 Q (pre-scaled by SCALE*LOG2E), K, V in (B,H,N,D)
__device__ unsigned g_Qt[BATCH*HEADS*SEQ*HD];
__device__ unsigned g_Kt[BATCH*HEADS*SEQ*HD];
__device__ unsigned g_Vt[BATCH*HEADS*SEQ*HD];
__device__ float    g_att_fallback[ROWS*CDIM];

// ---------------------------------------------------------------------------
// tf32 helpers
// ---------------------------------------------------------------------------
__device__ __forceinline__ unsigned f2tf32(float x) {
    unsigned u;
    asm("cvt.rna.tf32.f32 %0, %1;" : "=r"(u) : "f"(x));
    return u;
}

__device__ __forceinline__ void mma_tf32(float* d,
                                         unsigned a0, unsigned a1, unsigned a2, unsigned a3,
                                         unsigned b0, unsigned b1) {
    asm volatile(
        "mma.sync.aligned.m16n8k8.row.col.f32.tf32.tf32.f32 "
        "{%0,%1,%2,%3}, {%4,%5,%6,%7}, {%8,%9}, {%0,%1,%2,%3};"
        : "+f"(d[0]), "+f"(d[1]), "+f"(d[2]), "+f"(d[3])
        : "r"(a0), "r"(a1), "r"(a2), "r"(a3), "r"(b0), "r"(b1));
}

#define SAW 136

// ---------------------------------------------------------------------------
// Kernel 1: QKV GEMM (tf32 mma, round-4 structure) -> tf32 Q/K/V scatter
// ---------------------------------------------------------------------------
__global__ __launch_bounds__(128, 2) void qkv_tc(const float* __restrict__ X,
                                                 const float* __restrict__ W) {
    __shared__ unsigned sA[2][16][SAW];
    __shared__ unsigned sB[2][16][SAW];

    const int tid = threadIdx.x;
    const int lane = tid & 31;
    const int w = tid >> 5;
    const int g = lane >> 2, t = lane & 3;
    const int wm = w & 1, wn = w >> 1;

    const int m0 = blockIdx.y * 128;
    const int n0 = blockIdx.x * 128;

    float acc[4][8][4];
#pragma unroll
    for (int mt = 0; mt < 4; mt++)
#pragma unroll
        for (int nt = 0; nt < 8; nt++)
#pragma unroll
            for (int i = 0; i < 4; i++) acc[mt][nt][i] = 0.f;

    const int am = tid >> 2, at = tid & 3;
    const int bk = tid >> 5, bn = 4 * (tid & 31);

    const float* aptr = X + (size_t)(m0 + am) * CDIM + 4 * at;
    const float* bptr = W + (size_t)bk * QKVN + n0 + bn;

    float4 ra[4], rb[4];
#pragma unroll
    for (int i = 0; i < 4; i++) {
        ra[i] = *(const float4*)(aptr + (size_t)(32 * i) * CDIM);
        rb[i] = *(const float4*)(bptr + (size_t)(4 * i) * QKVN);
    }

    int buf = 0;
#pragma unroll
    for (int i = 0; i < 4; i++) {
        unsigned* da = &sA[0][4 * at][am + 32 * i];
        da[0 * SAW] = f2tf32(ra[i].x);
        da[1 * SAW] = f2tf32(ra[i].y);
        da[2 * SAW] = f2tf32(ra[i].z);
        da[3 * SAW] = f2tf32(ra[i].w);
        uint4 pb = make_uint4(f2tf32(rb[i].x), f2tf32(rb[i].y),
                              f2tf32(rb[i].z), f2tf32(rb[i].w));
        *(uint4*)&sB[0][bk + 4 * i][bn] = pb;
    }
    __syncthreads();

    for (int k0 = 16; k0 <= CDIM; k0 += 16) {
        if (k0 < CDIM) {
#pragma unroll
            for (int i = 0; i < 4; i++) {
                ra[i] = *(const float4*)(aptr + (size_t)(32 * i) * CDIM + k0);
                rb[i] = *(const float4*)(bptr + (size_t)(k0 + 4 * i) * QKVN);
            }
        }

#pragma unroll
        for (int kt = 0; kt < 2; kt++) {
            unsigned af[4][4];
#pragma unroll
            for (int mt = 0; mt < 4; mt++) {
                int mr = wm * 64 + mt * 16;
                af[mt][0] = sA[buf][kt * 8 + t][mr + g];
                af[mt][1] = sA[buf][kt * 8 + t][mr + g + 8];
                af[mt][2] = sA[buf][kt * 8 + t + 4][mr + g];
                af[mt][3] = sA[buf][kt * 8 + t + 4][mr + g + 8];
            }
#pragma unroll
            for (int nt = 0; nt < 8; nt++) {
                int nc = wn * 64 + nt * 8 + g;
                unsigned b0 = sB[buf][kt * 8 + t][nc];
                unsigned b1 = sB[buf][kt * 8 + t + 4][nc];
#pragma unroll
                for (int mt = 0; mt < 4; mt++)
                    mma_tf32(acc[mt][nt], af[mt][0], af[mt][1], af[mt][2], af[mt][3], b0, b1);
            }
        }

        if (k0 < CDIM) {
#pragma unroll
            for (int i = 0; i < 4; i++) {
                unsigned* da = &sA[buf ^ 1][4 * at][am + 32 * i];
                da[0 * SAW] = f2tf32(ra[i].x);
                da[1 * SAW] = f2tf32(ra[i].y);
                da[2 * SAW] = f2tf32(ra[i].z);
                da[3 * SAW] = f2tf32(ra[i].w);
                uint4 pb = make_uint4(f2tf32(rb[i].x), f2tf32(rb[i].y),
                                      f2tf32(rb[i].z), f2tf32(rb[i].w));
                *(uint4*)&sB[buf ^ 1][bk + 4 * i][bn] = pb;
            }
            __syncthreads();
            buf ^= 1;
        }
    }

    // scatter epilogue -> tf32 (Q pre-scaled)
    const float QF = SCALE * LOG2E;
#pragma unroll
    for (int mt = 0; mt < 4; mt++) {
#pragma unroll
        for (int nt = 0; nt < 8; nt++) {
            int col = n0 + wn * 64 + nt * 8 + 2 * t;
            int s = col >> 10;
            int h = (col >> 6) & 15;
            int dd = col & 63;
            unsigned* dst = (s == 0) ? g_Qt : (s == 1) ? g_Kt : g_Vt;
            float sc = (s == 0) ? QF : 1.f;
            int row0 = m0 + wm * 64 + mt * 16 + g;
#pragma unroll
            for (int half = 0; half < 2; half++) {
                int row = row0 + 8 * half;
                int b = row >> 11, n = row & 2047;
                unsigned* p = dst + ((((size_t)b * HEADS + h) * SEQ + n) * HD + dd);
                *(uint2*)p = make_uint2(f2tf32(acc[mt][nt][2 * half] * sc),
                                        f2tf32(acc[mt][nt][2 * half + 1] * sc));
            }
        }
    }
}

// ---------------------------------------------------------------------------
// Kernel 2: tensor-core flash attention; tf32 inputs, pure-copy tile fill.
// ---------------------------------------------------------------------------
#define SKS 68
#define SVS 72
#define FLASH_SMEM ((64*SKS + 64*SVS + 64*SKS) * 4)

__global__ __launch_bounds__(128) void flash_attn_tc(float* __restrict__ out2) {
    extern __shared__ unsigned smem[];
    unsigned* sK = smem;
    unsigned* sV = smem + 64 * SKS;
    unsigned* sP = smem + 64 * SKS + 64 * SVS;

    const int tid = threadIdx.x;
    const int lane = tid & 31;
    const int w = tid >> 5;
    const int g = lane >> 2;
    const int t = lane & 3;

    const int bh = blockIdx.y;
    const int q0 = blockIdx.x * 64;

    // Q fragments: already tf32 & pre-scaled
    unsigned qa[8][4];
    {
        const unsigned* p0 = g_Qt + ((size_t)bh * SEQ + (q0 + w * 16 + g)) * HD;
        const unsigned* p1 = p0 + 8 * HD;
#pragma unroll
        for (int kt = 0; kt < 8; kt++) {
            qa[kt][0] = p0[8 * kt + t];
            qa[kt][1] = p1[8 * kt + t];
            qa[kt][2] = p0[8 * kt + t + 4];
            qa[kt][3] = p1[8 * kt + t + 4];
        }
    }

    float o[8][4];
#pragma unroll
    for (int nt = 0; nt < 8; nt++)
#pragma unroll
        for (int i = 0; i < 4; i++) o[nt][i] = 0.f;
    float m0 = -1e30f, m1 = -1e30f, l0 = 0.f, l1 = 0.f;

    const uint4* Ksrc = (const uint4*)(g_Kt + (size_t)bh * SEQ * HD);
    const uint4* Vsrc = (const uint4*)(g_Vt + (size_t)bh * SEQ * HD);

    for (int kv = 0; kv < SEQ / 64; kv++) {
        __syncthreads();
#pragma unroll
        for (int i = 0; i < 8; i++) {
            int idx = tid + i * 128;
            int r = idx >> 4, c4 = (idx & 15) * 4;
            *(uint4*)(sK + r * SKS + c4) = Ksrc[kv * 1024 + idx];
            *(uint4*)(sV + r * SVS + c4) = Vsrc[kv * 1024 + idx];
        }
        __syncthreads();

        float s[8][4];
#pragma unroll
        for (int nt = 0; nt < 8; nt++)
#pragma unroll
            for (int i = 0; i < 4; i++) s[nt][i] = 0.f;

#pragma unroll
        for (int kt = 0; kt < 8; kt++) {
#pragma unroll
            for (int nt = 0; nt < 8; nt++) {
                unsigned b0 = sK[(8 * nt + g) * SKS + 8 * kt + t];
                unsigned b1 = sK[(8 * nt + g) * SKS + 8 * kt + t + 4];
                mma_tf32(s[nt], qa[kt][0], qa[kt][1], qa[kt][2], qa[kt][3], b0, b1);
            }
        }

        float rx0 = -1e30f, rx1 = -1e30f;
#pragma unroll
        for (int nt = 0; nt < 8; nt++) {
            rx0 = fmaxf(rx0, fmaxf(s[nt][0], s[nt][1]));
            rx1 = fmaxf(rx1, fmaxf(s[nt][2], s[nt][3]));
        }
        rx0 = fmaxf(rx0, __shfl_xor_sync(0xffffffffu, rx0, 1));
        rx0 = fmaxf(rx0, __shfl_xor_sync(0xffffffffu, rx0, 2));
        rx1 = fmaxf(rx1, __shfl_xor_sync(0xffffffffu, rx1, 1));
        rx1 = fmaxf(rx1, __shfl_xor_sync(0xffffffffu, rx1, 2));

        float nm0 = fmaxf(m0, rx0), nm1 = fmaxf(m1, rx1);
        float c0 = exp2f(m0 - nm0), c1 = exp2f(m1 - nm1);
        m0 = nm0; m1 = nm1;

        float ps0 = 0.f, ps1 = 0.f;
#pragma unroll
        for (int nt = 0; nt < 8; nt++) {
            s[nt][0] = exp2f(s[nt][0] - nm0);
            s[nt][1] = exp2f(s[nt][1] - nm0);
            s[nt][2] = exp2f(s[nt][2] - nm1);
            s[nt][3] = exp2f(s[nt][3] - nm1);
            ps0 += s[nt][0] + s[nt][1];
            ps1 += s[nt][2] + s[nt][3];
        }
        ps0 += __shfl_xor_sync(0xffffffffu, ps0, 1);
        ps0 += __shfl_xor_sync(0xffffffffu, ps0, 2);
        ps1 += __shfl_xor_sync(0xffffffffu, ps1, 1);
        ps1 += __shfl_xor_sync(0xffffffffu, ps1, 2);
        l0 = l0 * c0 + ps0;
        l1 = l1 * c1 + ps1;

#pragma unroll
        for (int nt = 0; nt < 8; nt++) {
            o[nt][0] *= c0; o[nt][1] *= c0;
            o[nt][2] *= c1; o[nt][3] *= c1;
        }

        unsigned* pr0 = sP + (w * 16 + g) * SKS;
        unsigned* pr1 = pr0 + 8 * SKS;
#pragma unroll
        for (int nt = 0; nt < 8; nt++) {
            *(uint2*)(pr0 + 8 * nt + 2 * t) = make_uint2(f2tf32(s[nt][0]), f2tf32(s[nt][1]));
            *(uint2*)(pr1 + 8 * nt + 2 * t) = make_uint2(f2tf32(s[nt][2]), f2tf32(s[nt][3]));
        }
        __syncwarp();

#pragma unroll
        for (int kt = 0; kt < 8; kt++) {
            unsigned pa0 = pr0[8 * kt + t];
            unsigned pa1 = pr1[8 * kt + t];
            unsigned pa2 = pr0[8 * kt + t + 4];
            unsigned pa3 = pr1[8 * kt + t + 4];
#pragma unroll
            for (int nt = 0; nt < 8; nt++) {
                unsigned b0 = sV[(8 * kt + t) * SVS + 8 * nt + g];
                unsigned b1 = sV[(8 * kt + t + 4) * SVS + 8 * nt + g];
                mma_tf32(o[nt], pa0, pa1, pa2, pa3, b0, b1);
            }
        }
    }

    const float inv0 = 1.f / l0, inv1 = 1.f / l1;
    const int b = bh >> 4, h = bh & 15;
    const int r0 = q0 + w * 16 + g;
    float* op0 = out2 + ((size_t)b * SEQ + r0) * CDIM + h * HD;
    float* op1 = op0 + (size_t)8 * CDIM;
#pragma unroll
    for (int nt = 0; nt < 8; nt++) {
        *(float2*)(op0 + 8 * nt + 2 * t) = make_float2(o[nt][0] * inv0, o[nt][1] * inv0);
        *(float2*)(op1 + 8 * nt + 2 * t) = make_float2(o[nt][2] * inv1, o[nt][3] * inv1);
    }
}

// ---------------------------------------------------------------------------
// Kernel 3: proj GEMM (round-4, unchanged). out = (att2 + f) @ W + b
// ---------------------------------------------------------------------------
__global__ __launch_bounds__(128, 2) void proj_tc(const float* __restrict__ att2,
                                                  const float* __restrict__ F,
                                                  const float* __restrict__ W,
                                                  const float* __restrict__ bias,
                                                  float* __restrict__ out) {
    __shared__ unsigned sA[2][16][SAW];
    __shared__ unsigned sB[2][16][SAW];

    const int tid = threadIdx.x;
    const int lane = tid & 31;
    const int w = tid >> 5;
    const int g = lane >> 2, t = lane & 3;
    const int wm = w & 1, wn = w >> 1;

    const int m0 = blockIdx.y * 128;
    const int n0 = blockIdx.x * 128;

    float acc[4][8][4];
#pragma unroll
    for (int mt = 0; mt < 4; mt++)
#pragma unroll
        for (int nt = 0; nt < 8; nt++)
#pragma unroll
            for (int i = 0; i < 4; i++) acc[mt][nt][i] = 0.f;

    const int am = tid >> 2, at = tid & 3;
    const int bk = tid >> 5, bn = 4 * (tid & 31);

    const float* aptr = att2 + (size_t)(m0 + am) * CDIM + 4 * at;
    const float* fptr = F + (size_t)(m0 + am) * CDIM + 4 * at;
    const float* bptr = W + (size_t)bk * CDIM + n0 + bn;

    float4 ra[4], rb[4];
#pragma unroll
    for (int i = 0; i < 4; i++) {
        float4 x = *(const float4*)(aptr + (size_t)(32 * i) * CDIM);
        float4 y = *(const float4*)(fptr + (size_t)(32 * i) * CDIM);
        ra[i] = make_float4(x.x + y.x, x.y + y.y, x.z + y.z, x.w + y.w);
        rb[i] = *(const float4*)(bptr + (size_t)(4 * i) * CDIM);
    }

    int buf = 0;
#pragma unroll
    for (int i = 0; i < 4; i++) {
        unsigned* da = &sA[0][4 * at][am + 32 * i];
        da[0 * SAW] = f2tf32(ra[i].x);
        da[1 * SAW] = f2tf32(ra[i].y);
        da[2 * SAW] = f2tf32(ra[i].z);
        da[3 * SAW] = f2tf32(ra[i].w);
        uint4 pb = make_uint4(f2tf32(rb[i].x), f2tf32(rb[i].y),
                              f2tf32(rb[i].z), f2tf32(rb[i].w));
        *(uint4*)&sB[0][bk + 4 * i][bn] = pb;
    }
    __syncthreads();

    for (int k0 = 16; k0 <= CDIM; k0 += 16) {
        if (k0 < CDIM) {
#pragma unroll
            for (int i = 0; i < 4; i++) {
                float4 x = *(const float4*)(aptr + (size_t)(32 * i) * CDIM + k0);
                float4 y = *(const float4*)(fptr + (size_t)(32 * i) * CDIM + k0);
                ra[i] = make_float4(x.x + y.x, x.y + y.y, x.z + y.z, x.w + y.w);
                rb[i] = *(const float4*)(bptr + (size_t)(k0 + 4 * i) * CDIM);
            }
        }

#pragma unroll
        for (int kt = 0; kt < 2; kt++) {
            unsigned af[4][4];
#pragma unroll
            for (int mt = 0; mt < 4; mt++) {
                int mr = wm * 64 + mt * 16;
                af[mt][0] = sA[buf][kt * 8 + t][mr + g];
                af[mt][1] = sA[buf][kt * 8 + t][mr + g + 8];
                af[mt][2] = sA[buf][kt * 8 + t + 4][mr + g];
                af[mt][3] = sA[buf][kt * 8 + t + 4][mr + g + 8];
            }
#pragma unroll
            for (int nt = 0; nt < 8; nt++) {
                int nc = wn * 64 + nt * 8 + g;
                unsigned b0 = sB[buf][kt * 8 + t][nc];
                unsigned b1 = sB[buf][kt * 8 + t + 4][nc];
#pragma unroll
                for (int mt = 0; mt < 4; mt++)
                    mma_tf32(acc[mt][nt], af[mt][0], af[mt][1], af[mt][2], af[mt][3], b0, b1);
            }
        }

        if (k0 < CDIM) {
#pragma unroll
            for (int i = 0; i < 4; i++) {
                unsigned* da = &sA[buf ^ 1][4 * at][am + 32 * i];
                da[0 * SAW] = f2tf32(ra[i].x);
                da[1 * SAW] = f2tf32(ra[i].y);
                da[2 * SAW] = f2tf32(ra[i].z);
                da[3 * SAW] = f2tf32(ra[i].w);
                uint4 pb = make_uint4(f2tf32(rb[i].x), f2tf32(rb[i].y),
                                      f2tf32(rb[i].z), f2tf32(rb[i].w));
                *(uint4*)&sB[buf ^ 1][bk + 4 * i][bn] = pb;
            }
            __syncthreads();
            buf ^= 1;
        }
    }

#pragma unroll
    for (int mt = 0; mt < 4; mt++) {
#pragma unroll
        for (int nt = 0; nt < 8; nt++) {
            int col = n0 + wn * 64 + nt * 8 + 2 * t;
            float2 bb = *(const float2*)&bias[col];
            int row0 = m0 + wm * 64 + mt * 16 + g;
            float* p0 = out + (size_t)row0 * CDIM + col;
            float* p1 = out + (size_t)(row0 + 8) * CDIM + col;
            *(float2*)p0 = make_float2(acc[mt][nt][0] + bb.x, acc[mt][nt][1] + bb.y);
            *(float2*)p1 = make_float2(acc[mt][nt][2] + bb.x, acc[mt][nt][3] + bb.y);
        }
    }
}

extern "C" void kernel_launch(void* const* d_in, const int* in_sizes, int n_in,
                              void* d_out, int out_size) {
    const float* x     = (const float*)d_in[0];
    const float* f     = (const float*)d_in[1];
    const float* Wqkv  = (const float*)d_in[2];
    const float* Wproj = (const float*)d_in[3];
    const float* bproj = (const float*)d_in[4];
    float* out = (float*)d_out;

    const size_t half = (size_t)BATCH * SEQ * CDIM;
    float* att2;
    if ((size_t)out_size >= 2 * half) {
        att2 = out + half;
    } else {
        cudaGetSymbolAddress((void**)&att2, g_att_fallback);
    }

    cudaFuncSetAttribute(flash_attn_tc, cudaFuncAttributeMaxDynamicSharedMemorySize,
                         FLASH_SMEM);

    qkv_tc<<<dim3(QKVN / 128, ROWS / 128), 128>>>(x, Wqkv);
    flash_attn_tc<<<dim3(SEQ / 64, BHN), 128, FLASH_SMEM>>>(att2);
    proj_tc<<<dim3(CDIM / 128, ROWS / 128), 128>>>(att2, f, Wproj, bproj, out);
}